// round 2
// baseline (speedup 1.0000x reference)
#include <cuda_runtime.h>
#include <math.h>

#define B_SZ   4
#define LSEQ   2048
#define DMODEL 1024
#define DINNER 2048
#define DHALF  1024
#define DSTATE 16
#define DTRANK 64
#define XDBL_C 96
#define MROWS  (B_SZ * LSEQ)   // 8192

// ---------------- scratch (static device arrays; no allocation) ----------------
__device__ float g_xz[(size_t)MROWS * DINNER];    // 64 MB : x @ W_in
__device__ float g_xs[(size_t)MROWS * DHALF];     // 32 MB : silu(conv(xs))
__device__ float g_xdbl[(size_t)MROWS * XDBL_C];  //  3 MB : xs @ W_xdbl
__device__ float g_delta[(size_t)MROWS * DHALF];  // 32 MB : softplus(dt + 2*inv_dt)
__device__ float g_cat[(size_t)MROWS * DINNER];   // 64 MB : [y | z]

// ---------------- epilogues ----------------
// EPI 0: none, EPI 1: + bias[col], EPI 2: softplus(acc + 2*bias[col])
template <int EPI>
__device__ __forceinline__ float apply_epi(float acc, const float* __restrict__ bias, int col) {
    if (EPI == 1) return acc + bias[col];
    if (EPI == 2) {
        float v = acc + 2.0f * bias[col];
        return fmaxf(v, 0.0f) + log1pf(expf(-fabsf(v)));  // stable softplus
    }
    return acc;
}

// ---------------- tiled fp32 SGEMM: C[M,N] = A[M,K] @ B[K,N] (+epilogue) ----------------
// BM=BN=128, BK=8, 256 threads, 8x8 per thread. Requires M % 128 == 0, K % 8 == 0,
// lda/ldb/ldc such that float4 loads stay 16B-aligned (all our lds are multiples of 4).
template <int EPI>
__global__ __launch_bounds__(256)
void sgemm128(const float* __restrict__ A, const float* __restrict__ B,
              float* __restrict__ C, const float* __restrict__ bias,
              int M, int N, int K, int lda, int ldb, int ldc)
{
    __shared__ float As[8][128];
    __shared__ float Bs[8][128];

    const int bx = blockIdx.x;       // N tile
    const int by = blockIdx.y;       // M tile
    const int tid = threadIdx.x;
    const int tx = tid & 15;         // 0..15
    const int ty = tid >> 4;         // 0..15

    const int rowA = tid >> 1;            // 0..127
    const int colA = (tid & 1) * 4;       // 0 or 4
    const int rowB = tid >> 5;            // 0..7
    const int colB = (tid & 31) * 4;      // 0..124

    const int gArow = by * 128 + rowA;
    const int gBcol = bx * 128 + colB;

    float acc[8][8];
#pragma unroll
    for (int i = 0; i < 8; ++i)
#pragma unroll
        for (int j = 0; j < 8; ++j) acc[i][j] = 0.0f;

    for (int k0 = 0; k0 < K; k0 += 8) {
        float4 av = make_float4(0.f, 0.f, 0.f, 0.f);
        av = *reinterpret_cast<const float4*>(A + (size_t)gArow * lda + k0 + colA);
        As[colA + 0][rowA] = av.x;
        As[colA + 1][rowA] = av.y;
        As[colA + 2][rowA] = av.z;
        As[colA + 3][rowA] = av.w;

        float4 bv = make_float4(0.f, 0.f, 0.f, 0.f);
        if (gBcol < N)
            bv = *reinterpret_cast<const float4*>(B + (size_t)(k0 + rowB) * ldb + gBcol);
        *reinterpret_cast<float4*>(&Bs[rowB][colB]) = bv;

        __syncthreads();

#pragma unroll
        for (int kk = 0; kk < 8; ++kk) {
            float4 a0 = *reinterpret_cast<const float4*>(&As[kk][ty * 8]);
            float4 a1 = *reinterpret_cast<const float4*>(&As[kk][ty * 8 + 4]);
            float4 b0 = *reinterpret_cast<const float4*>(&Bs[kk][tx * 8]);
            float4 b1 = *reinterpret_cast<const float4*>(&Bs[kk][tx * 8 + 4]);
            float ar[8] = {a0.x, a0.y, a0.z, a0.w, a1.x, a1.y, a1.z, a1.w};
            float br[8] = {b0.x, b0.y, b0.z, b0.w, b1.x, b1.y, b1.z, b1.w};
#pragma unroll
            for (int i = 0; i < 8; ++i)
#pragma unroll
                for (int j = 0; j < 8; ++j)
                    acc[i][j] = fmaf(ar[i], br[j], acc[i][j]);
        }
        __syncthreads();
    }

#pragma unroll
    for (int i = 0; i < 8; ++i) {
        int row = by * 128 + ty * 8 + i;
        float* crow = C + (size_t)row * ldc;
#pragma unroll
        for (int j = 0; j < 8; ++j) {
            int col = bx * 128 + tx * 8 + j;
            if (col < N) crow[col] = apply_epi<EPI>(acc[i][j], bias, col);
        }
    }
}

// ---------------- depthwise conv (k=4, SAME: pad_lo=1) + SiLU ----------------
// Reads from g_xz (row-major [b*L, 2048]) at column offset col_off.
// Writes to out[(b*L + t)*out_ld + out_coloff + c].
__global__ __launch_bounds__(256)
void conv_silu_kernel(int col_off, const float* __restrict__ w,
                      const float* __restrict__ bias,
                      float* __restrict__ out, int out_ld, int out_coloff)
{
    __shared__ float tile[67][128];   // t0-1 .. t0+65

    const int c_t = blockIdx.x;   // 0..7 (128-wide channel tile)
    const int t_t = blockIdx.y;   // 0..31 (64-wide time tile)
    const int b   = blockIdx.z;   // 0..3
    const int tx  = threadIdx.x;  // 0..127 channel within tile
    const int ty  = threadIdx.y;  // 0..1

    const int c  = c_t * 128 + tx;
    const int t0 = t_t * 64;

    const float* src = g_xz + (size_t)b * LSEQ * DINNER + col_off + c;
    for (int r = ty; r < 67; r += 2) {
        int t = t0 + r - 1;
        tile[r][tx] = (t >= 0 && t < LSEQ) ? src[(size_t)t * DINNER] : 0.0f;
    }
    __syncthreads();

    const float w0 = w[c];
    const float w1 = w[DHALF + c];
    const float w2 = w[2 * DHALF + c];
    const float w3 = w[3 * DHALF + c];
    const float bb = bias[c];

    float* dst = out + (size_t)b * LSEQ * out_ld + out_coloff + c;
    for (int tt = ty; tt < 64; tt += 2) {
        float v = bb;
        v = fmaf(w0, tile[tt + 0][tx], v);
        v = fmaf(w1, tile[tt + 1][tx], v);
        v = fmaf(w2, tile[tt + 2][tx], v);
        v = fmaf(w3, tile[tt + 3][tx], v);
        float s = v / (1.0f + expf(-v));        // SiLU
        dst[(size_t)(t0 + tt) * out_ld] = s;
    }
}

// ---------------- selective scan ----------------
// One 16-lane group per channel (b,d); lane = state index n; A[n] = -(n+1).
// h_t = exp(A_n * delta) * h + (delta*u)*B_n ; y = sum_n h*C_n ; out = y + u*D[d]
__global__ __launch_bounds__(256)
void scan_kernel(const float* __restrict__ Dvec)
{
    const int grp = blockIdx.x * 16 + (threadIdx.x >> 4);   // 0..4095
    const int n   = threadIdx.x & 15;
    const int b   = grp >> 10;
    const int d   = grp & 1023;

    const float An = -(float)(n + 1);
    const float Dd = Dvec[d];

    const float* pD = g_delta + (size_t)b * LSEQ * DHALF + d;
    const float* pU = g_xs    + (size_t)b * LSEQ * DHALF + d;
    const float* pB = g_xdbl  + (size_t)b * LSEQ * XDBL_C + DTRANK + n;
    const float* pC = pB + DSTATE;
    float*       pY = g_cat   + (size_t)b * LSEQ * DINNER + d;

    float h = 0.0f;
    for (int t0 = 0; t0 < LSEQ; t0 += 8) {
        float dv[8], uv[8], Bv[8], Cv[8];
#pragma unroll
        for (int i = 0; i < 8; ++i) {
            dv[i] = pD[(size_t)(t0 + i) * DHALF];
            uv[i] = pU[(size_t)(t0 + i) * DHALF];
            Bv[i] = pB[(size_t)(t0 + i) * XDBL_C];
            Cv[i] = pC[(size_t)(t0 + i) * XDBL_C];
        }
#pragma unroll
        for (int i = 0; i < 8; ++i) {
            float dA = __expf(An * dv[i]);
            h = fmaf(dA, h, dv[i] * uv[i] * Bv[i]);
            float v = h * Cv[i];
            v += __shfl_xor_sync(0xffffffffu, v, 1);
            v += __shfl_xor_sync(0xffffffffu, v, 2);
            v += __shfl_xor_sync(0xffffffffu, v, 4);
            v += __shfl_xor_sync(0xffffffffu, v, 8);
            if (n == 0) pY[(size_t)(t0 + i) * DINNER] = fmaf(uv[i], Dd, v);
        }
    }
}

// ---------------- launch ----------------
extern "C" void kernel_launch(void* const* d_in, const int* in_sizes, int n_in,
                              void* d_out, int out_size)
{
    const float* x      = (const float*)d_in[0];
    const float* W_in   = (const float*)d_in[1];
    const float* cxw    = (const float*)d_in[2];
    const float* cxb    = (const float*)d_in[3];
    const float* czw    = (const float*)d_in[4];
    const float* czb    = (const float*)d_in[5];
    const float* W_xdbl = (const float*)d_in[6];
    const float* W_dt   = (const float*)d_in[7];
    const float* inv_dt = (const float*)d_in[8];
    const float* Dv     = (const float*)d_in[9];
    const float* W_out  = (const float*)d_in[10];
    const float* b_out  = (const float*)d_in[11];
    float* out = (float*)d_out;

    float *xz, *xs, *xdbl, *delta, *cat;
    cudaGetSymbolAddress((void**)&xz,    g_xz);
    cudaGetSymbolAddress((void**)&xs,    g_xs);
    cudaGetSymbolAddress((void**)&xdbl,  g_xdbl);
    cudaGetSymbolAddress((void**)&delta, g_delta);
    cudaGetSymbolAddress((void**)&cat,   g_cat);

    // 1) xz = x @ W_in                       (8192 x 2048, K=1024)
    sgemm128<0><<<dim3(DINNER / 128, MROWS / 128), 256>>>(
        x, W_in, xz, nullptr, MROWS, DINNER, DMODEL, DMODEL, DINNER, DINNER);

    // 2) depthwise conv + SiLU on both halves
    conv_silu_kernel<<<dim3(8, 32, 4), dim3(128, 2)>>>(0,     cxw, cxb, xs,  DHALF,  0);
    conv_silu_kernel<<<dim3(8, 32, 4), dim3(128, 2)>>>(DHALF, czw, czb, cat, DINNER, DHALF);

    // 3) x_dbl = xs @ W_xdbl                 (8192 x 96, K=1024)
    sgemm128<0><<<dim3(1, MROWS / 128), 256>>>(
        xs, W_xdbl, xdbl, nullptr, MROWS, XDBL_C, DHALF, DHALF, XDBL_C, XDBL_C);

    // 4) delta = softplus(dt_low @ W_dt + 2*inv_dt)   (8192 x 1024, K=64, lda=96)
    sgemm128<2><<<dim3(DHALF / 128, MROWS / 128), 256>>>(
        xdbl, W_dt, delta, inv_dt, MROWS, DHALF, DTRANK, XDBL_C, DHALF, DHALF);

    // 5) selective scan -> y into g_cat[:, 0:1024]
    scan_kernel<<<256, 256>>>(Dv);

    // 6) out = [y | z] @ W_out + b_out       (8192 x 1024, K=2048)
    sgemm128<1><<<dim3(DMODEL / 128, MROWS / 128), 256>>>(
        cat, W_out, out, b_out, MROWS, DMODEL, DINNER, DINNER, DMODEL, DMODEL);
}

// round 7
// speedup vs baseline: 2.5201x; 2.5201x over previous
#include <cuda_runtime.h>
#include <cstdint>
#include <math.h>

#define B_SZ   4
#define LSEQ   2048
#define DMODEL 1024
#define DINNER 2048
#define DHALF  1024
#define DSTATE 16
#define DTRANK 64
#define XDBL_C 96
#define MROWS  (B_SZ * LSEQ)   // 8192

// ---------------- scratch (static device arrays; no allocation) ----------------
__device__ float g_xz[(size_t)MROWS * DINNER];
__device__ float g_xs[(size_t)MROWS * DHALF];
__device__ float g_xdbl[(size_t)MROWS * XDBL_C];
__device__ float g_delta[(size_t)MROWS * DHALF];
__device__ float g_cat[(size_t)MROWS * DINNER];
__device__ float g_WinT [(size_t)DINNER * DMODEL];
__device__ float g_WxT  [(size_t)XDBL_C * DHALF];
__device__ float g_WdtT [(size_t)DHALF * DTRANK];
__device__ float g_WoutT[(size_t)DMODEL * DINNER];

// ================= helpers =================
__device__ __forceinline__ uint32_t smem_u32(const void* p) {
    uint32_t a;
    asm("{ .reg .u64 t; cvta.to.shared.u64 t, %1; cvt.u32.u64 %0, t; }" : "=r"(a) : "l"(p));
    return a;
}
__device__ __forceinline__ void cp16(uint32_t dst, const void* src) {
    asm volatile("cp.async.cg.shared.global [%0], [%1], 16;" :: "r"(dst), "l"(src));
}
#define CP_COMMIT() asm volatile("cp.async.commit_group;" ::: "memory")
#define CP_WAIT(n)  asm volatile("cp.async.wait_group %0;" :: "n"(n) : "memory")

__device__ __forceinline__ uint32_t f2tf(float f) {
    uint32_t u; asm("cvt.rna.tf32.f32 %0, %1;" : "=r"(u) : "f"(f)); return u;
}
__device__ __forceinline__ void mma_tf32(float* c, const uint32_t* a, const uint32_t* b) {
    asm volatile(
        "mma.sync.aligned.m16n8k8.row.col.f32.tf32.tf32.f32 "
        "{%0,%1,%2,%3}, {%4,%5,%6,%7}, {%8,%9}, {%0,%1,%2,%3};"
        : "+f"(c[0]), "+f"(c[1]), "+f"(c[2]), "+f"(c[3])
        : "r"(a[0]), "r"(a[1]), "r"(a[2]), "r"(a[3]), "r"(b[0]), "r"(b[1]));
}

// ---------------- epilogues ----------------
template <int EPI>
__device__ __forceinline__ float apply_epi(float acc, const float* __restrict__ bias, int col) {
    if (EPI == 1) return acc + bias[col];
    if (EPI == 2) {
        float v = acc + 2.0f * bias[col];
        return fmaxf(v, 0.0f) + log1pf(expf(-fabsf(v)));
    }
    return acc;
}

// ================= tf32 mma.sync GEMM =================
// C[M,N] = A[M,K] @ Bt[N,K]^T. CTA 128x128, BK=32, 256 thr, warp tile 64x32.
// Smem: A/B tiles stored as [row][32 floats], 16B chunks XOR-swizzled by (row&7).
#define GSM_STAGE 4096                       // floats per tile stage (128*32)
#define GSM_TOTAL (4 * GSM_STAGE * 4)        // bytes: 2 stages A + 2 stages B

template <int EPI>
__global__ __launch_bounds__(256)
void gemm_mma(const float* __restrict__ A, const float* __restrict__ Bt,
              float* __restrict__ C, const float* __restrict__ bias,
              int M, int N, int K, int lda, int ldb, int ldc)
{
    extern __shared__ float sm[];
    float* sA = sm;                  // 2 x 4096 floats
    float* sB = sm + 2 * GSM_STAGE;  // 2 x 4096 floats

    const int tid = threadIdx.x;
    const int wid = tid >> 5, lane = tid & 31;
    const int g = lane >> 2, tg = lane & 3;
    const int wm = wid & 1, wn = wid >> 1;      // 2 x 4 warp grid
    const int row0 = blockIdx.y * 128;
    const int col0 = blockIdx.x * 128;

    float acc[4][4][4];
#pragma unroll
    for (int i = 0; i < 4; ++i)
#pragma unroll
        for (int j = 0; j < 4; ++j)
#pragma unroll
            for (int c = 0; c < 4; ++c) acc[i][j][c] = 0.0f;

    const uint32_t sAu = smem_u32(sA);
    const uint32_t sBu = smem_u32(sB);

    // copy one BK-tile (stage s) of A and B
    const int cm = tid >> 3, cc = tid & 7;   // this thread's base row/chunk
    auto load_stage = [&](int s, int kt) {
        uint32_t ab = sAu + s * (GSM_STAGE * 4);
        uint32_t bb = sBu + s * (GSM_STAGE * 4);
        const int k0 = kt * 32;
#pragma unroll
        for (int i = 0; i < 4; ++i) {
            int m = cm + i * 32;
            cp16(ab + m * 128 + ((cc ^ (m & 7)) * 16),
                 A + (size_t)(row0 + m) * lda + k0 + cc * 4);
        }
#pragma unroll
        for (int i = 0; i < 4; ++i) {
            int n = cm + i * 32;
            if (col0 + n < N)
                cp16(bb + n * 128 + ((cc ^ (n & 7)) * 16),
                     Bt + (size_t)(col0 + n) * ldb + k0 + cc * 4);
        }
    };

    const int KT = K >> 5;
    load_stage(0, 0); CP_COMMIT();

    // precompute per-thread smem row bases (in floats)
    int am[4][2];
#pragma unroll
    for (int mt = 0; mt < 4; ++mt) {
        am[mt][0] = (wm * 64 + mt * 16 + g) * 32;
        am[mt][1] = (wm * 64 + mt * 16 + g + 8) * 32;
    }
    int bn[4];
#pragma unroll
    for (int nt = 0; nt < 4; ++nt) bn[nt] = (wn * 32 + nt * 8 + g) * 32;

    for (int kt = 0; kt < KT; ++kt) {
        const int s = kt & 1;
        if (kt + 1 < KT) { load_stage(s ^ 1, kt + 1); CP_COMMIT(); CP_WAIT(1); }
        else            { CP_WAIT(0); }
        __syncthreads();

        const float* a_s = sA + s * GSM_STAGE;
        const float* b_s = sB + s * GSM_STAGE;
#pragma unroll
        for (int ks = 0; ks < 4; ++ks) {
            const int sw0 = ((2 * ks) ^ g) * 4 + tg;       // swizzled offset, kgroup even
            const int sw1 = ((2 * ks + 1) ^ g) * 4 + tg;   // kgroup odd
            uint32_t afr[4][4], bfr[4][2];
#pragma unroll
            for (int mt = 0; mt < 4; ++mt) {
                afr[mt][0] = f2tf(a_s[am[mt][0] + sw0]);
                afr[mt][1] = f2tf(a_s[am[mt][1] + sw0]);
                afr[mt][2] = f2tf(a_s[am[mt][0] + sw1]);
                afr[mt][3] = f2tf(a_s[am[mt][1] + sw1]);
            }
#pragma unroll
            for (int nt = 0; nt < 4; ++nt) {
                bfr[nt][0] = f2tf(b_s[bn[nt] + sw0]);
                bfr[nt][1] = f2tf(b_s[bn[nt] + sw1]);
            }
#pragma unroll
            for (int mt = 0; mt < 4; ++mt)
#pragma unroll
                for (int nt = 0; nt < 4; ++nt)
                    mma_tf32(acc[mt][nt], afr[mt], bfr[nt]);
        }
        __syncthreads();
    }

    // epilogue
#pragma unroll
    for (int mt = 0; mt < 4; ++mt) {
#pragma unroll
        for (int h = 0; h < 2; ++h) {
            const int row = row0 + wm * 64 + mt * 16 + g + h * 8;
            float* cr = C + (size_t)row * ldc;
#pragma unroll
            for (int nt = 0; nt < 4; ++nt) {
                const int col = col0 + wn * 32 + nt * 8 + tg * 2;
                if (col < N) {
                    float2 v;
                    v.x = apply_epi<EPI>(acc[mt][nt][h * 2 + 0], bias, col);
                    v.y = apply_epi<EPI>(acc[mt][nt][h * 2 + 1], bias, col + 1);
                    *reinterpret_cast<float2*>(cr + col) = v;
                }
            }
        }
    }
}

// ================= transpose: out[c][r] = in[r][c] =================
__global__ __launch_bounds__(256)
void transpose_kernel(const float* __restrict__ in, float* __restrict__ out, int R, int Cc)
{
    __shared__ float t[32][33];
    const int r0 = blockIdx.y * 32, c0 = blockIdx.x * 32;
    const int tx = threadIdx.x, ty = threadIdx.y;
    for (int j = ty; j < 32; j += 8)
        if (r0 + j < R && c0 + tx < Cc)
            t[j][tx] = in[(size_t)(r0 + j) * Cc + c0 + tx];
    __syncthreads();
    for (int j = ty; j < 32; j += 8)
        if (c0 + j < Cc && r0 + tx < R)
            out[(size_t)(c0 + j) * R + r0 + tx] = t[tx][j];
}

// ================= depthwise conv (k=4, SAME pad_lo=1) + SiLU =================
__global__ __launch_bounds__(256)
void conv_silu_kernel(int col_off, const float* __restrict__ w,
                      const float* __restrict__ bias,
                      float* __restrict__ out, int out_ld, int out_coloff)
{
    __shared__ float tile[67][128];
    const int c_t = blockIdx.x, t_t = blockIdx.y, b = blockIdx.z;
    const int tx = threadIdx.x, ty = threadIdx.y;
    const int c = c_t * 128 + tx;
    const int t0 = t_t * 64;

    const float* src = g_xz + (size_t)b * LSEQ * DINNER + col_off + c;
    for (int r = ty; r < 67; r += 2) {
        int t = t0 + r - 1;
        tile[r][tx] = (t >= 0 && t < LSEQ) ? src[(size_t)t * DINNER] : 0.0f;
    }
    __syncthreads();

    const float w0 = w[c], w1 = w[DHALF + c], w2 = w[2 * DHALF + c], w3 = w[3 * DHALF + c];
    const float bb = bias[c];
    float* dst = out + (size_t)b * LSEQ * out_ld + out_coloff + c;
    for (int tt = ty; tt < 64; tt += 2) {
        float v = bb;
        v = fmaf(w0, tile[tt + 0][tx], v);
        v = fmaf(w1, tile[tt + 1][tx], v);
        v = fmaf(w2, tile[tt + 2][tx], v);
        v = fmaf(w3, tile[tt + 3][tx], v);
        dst[(size_t)(t0 + tt) * out_ld] = v / (1.0f + expf(-v));
    }
}

// ================= selective scan =================
__global__ __launch_bounds__(256)
void scan_kernel(const float* __restrict__ Dvec)
{
    const int grp = blockIdx.x * 16 + (threadIdx.x >> 4);
    const int n = threadIdx.x & 15;
    const int b = grp >> 10;
    const int d = grp & 1023;

    const float An = -(float)(n + 1);
    const float Dd = Dvec[d];

    const float* pD = g_delta + (size_t)b * LSEQ * DHALF + d;
    const float* pU = g_xs    + (size_t)b * LSEQ * DHALF + d;
    const float* pB = g_xdbl  + (size_t)b * LSEQ * XDBL_C + DTRANK + n;
    const float* pC = pB + DSTATE;
    float*       pY = g_cat   + (size_t)b * LSEQ * DINNER + d;

    float h = 0.0f;
    for (int t0 = 0; t0 < LSEQ; t0 += 8) {
        float dv[8], uv[8], Bv[8], Cv[8];
#pragma unroll
        for (int i = 0; i < 8; ++i) {
            dv[i] = pD[(size_t)(t0 + i) * DHALF];
            uv[i] = pU[(size_t)(t0 + i) * DHALF];
            Bv[i] = pB[(size_t)(t0 + i) * XDBL_C];
            Cv[i] = pC[(size_t)(t0 + i) * XDBL_C];
        }
#pragma unroll
        for (int i = 0; i < 8; ++i) {
            float dA = __expf(An * dv[i]);
            h = fmaf(dA, h, dv[i] * uv[i] * Bv[i]);
            float v = h * Cv[i];
            v += __shfl_xor_sync(0xffffffffu, v, 1);
            v += __shfl_xor_sync(0xffffffffu, v, 2);
            v += __shfl_xor_sync(0xffffffffu, v, 4);
            v += __shfl_xor_sync(0xffffffffu, v, 8);
            if (n == 0) pY[(size_t)(t0 + i) * DINNER] = fmaf(uv[i], Dd, v);
        }
    }
}

// ================= launch =================
extern "C" void kernel_launch(void* const* d_in, const int* in_sizes, int n_in,
                              void* d_out, int out_size)
{
    const float* x      = (const float*)d_in[0];
    const float* W_in   = (const float*)d_in[1];
    const float* cxw    = (const float*)d_in[2];
    const float* cxb    = (const float*)d_in[3];
    const float* czw    = (const float*)d_in[4];
    const float* czb    = (const float*)d_in[5];
    const float* W_xdbl = (const float*)d_in[6];
    const float* W_dt   = (const float*)d_in[7];
    const float* inv_dt = (const float*)d_in[8];
    const float* Dv     = (const float*)d_in[9];
    const float* W_out  = (const float*)d_in[10];
    const float* b_out  = (const float*)d_in[11];
    float* out = (float*)d_out;

    float *xz, *xs, *xdbl, *delta, *cat, *WinT, *WxT, *WdtT, *WoutT;
    cudaGetSymbolAddress((void**)&xz,    g_xz);
    cudaGetSymbolAddress((void**)&xs,    g_xs);
    cudaGetSymbolAddress((void**)&xdbl,  g_xdbl);
    cudaGetSymbolAddress((void**)&delta, g_delta);
    cudaGetSymbolAddress((void**)&cat,   g_cat);
    cudaGetSymbolAddress((void**)&WinT,  g_WinT);
    cudaGetSymbolAddress((void**)&WxT,   g_WxT);
    cudaGetSymbolAddress((void**)&WdtT,  g_WdtT);
    cudaGetSymbolAddress((void**)&WoutT, g_WoutT);

    cudaFuncSetAttribute(gemm_mma<0>, cudaFuncAttributeMaxDynamicSharedMemorySize, GSM_TOTAL);
    cudaFuncSetAttribute(gemm_mma<1>, cudaFuncAttributeMaxDynamicSharedMemorySize, GSM_TOTAL);
    cudaFuncSetAttribute(gemm_mma<2>, cudaFuncAttributeMaxDynamicSharedMemorySize, GSM_TOTAL);

    // 0) transpose weights -> [N][K] K-major
    transpose_kernel<<<dim3(DINNER / 32, DMODEL / 32), dim3(32, 8)>>>(W_in, WinT, DMODEL, DINNER);
    transpose_kernel<<<dim3(XDBL_C / 32, DHALF / 32), dim3(32, 8)>>>(W_xdbl, WxT, DHALF, XDBL_C);
    transpose_kernel<<<dim3(DHALF / 32, DTRANK / 32), dim3(32, 8)>>>(W_dt, WdtT, DTRANK, DHALF);
    transpose_kernel<<<dim3(DMODEL / 32, DINNER / 32), dim3(32, 8)>>>(W_out, WoutT, DINNER, DMODEL);

    // 1) xz = x @ W_in        (8192 x 2048, K=1024)
    gemm_mma<0><<<dim3(DINNER / 128, MROWS / 128), 256, GSM_TOTAL>>>(
        x, WinT, xz, nullptr, MROWS, DINNER, DMODEL, DMODEL, DMODEL, DINNER);

    // 2) depthwise conv + SiLU
    conv_silu_kernel<<<dim3(8, 32, 4), dim3(128, 2)>>>(0,     cxw, cxb, xs,  DHALF,  0);
    conv_silu_kernel<<<dim3(8, 32, 4), dim3(128, 2)>>>(DHALF, czw, czb, cat, DINNER, DHALF);

    // 3) x_dbl = xs @ W_xdbl  (8192 x 96, K=1024)
    gemm_mma<0><<<dim3(1, MROWS / 128), 256, GSM_TOTAL>>>(
        xs, WxT, xdbl, nullptr, MROWS, XDBL_C, DHALF, DHALF, DHALF, XDBL_C);

    // 4) delta = softplus(dt_low @ W_dt + 2*inv_dt)   (8192 x 1024, K=64)
    gemm_mma<2><<<dim3(DHALF / 128, MROWS / 128), 256, GSM_TOTAL>>>(
        xdbl, WdtT, delta, inv_dt, MROWS, DHALF, DTRANK, XDBL_C, DTRANK, DHALF);

    // 5) selective scan -> y into g_cat[:, 0:1024]
    scan_kernel<<<256, 256>>>(Dv);

    // 6) out = [y | z] @ W_out + b_out   (8192 x 1024, K=2048)
    gemm_mma<1><<<dim3(DMODEL / 128, MROWS / 128), 256, GSM_TOTAL>>>(
        cat, WoutT, out, b_out, MROWS, DMODEL, DINNER, DINNER, DINNER, DMODEL);
}

// round 8
// speedup vs baseline: 2.7157x; 1.0776x over previous
#include <cuda_runtime.h>
#include <cstdint>
#include <math.h>

#define B_SZ   4
#define LSEQ   2048
#define DMODEL 1024
#define DINNER 2048
#define DHALF  1024
#define DSTATE 16
#define DTRANK 64
#define XDBL_C 96
#define MROWS  (B_SZ * LSEQ)   // 8192

// ---------------- scratch (static device arrays; no allocation) ----------------
__device__ float g_xr[(size_t)MROWS * DMODEL];    // tf32-rounded x
__device__ float g_xz[(size_t)MROWS * DINNER];
__device__ float g_xs[(size_t)MROWS * DHALF];
__device__ float g_xdbl[(size_t)MROWS * XDBL_C];
__device__ float g_delta[(size_t)MROWS * DHALF];
__device__ float g_cat[(size_t)MROWS * DINNER];
__device__ float g_WinT [(size_t)DINNER * DMODEL];
__device__ float g_WxT  [(size_t)XDBL_C * DHALF];
__device__ float g_WdtT [(size_t)DHALF * DTRANK];
__device__ float g_WoutT[(size_t)DMODEL * DINNER];

// ================= helpers =================
__device__ __forceinline__ uint32_t smem_u32(const void* p) {
    uint32_t a;
    asm("{ .reg .u64 t; cvta.to.shared.u64 t, %1; cvt.u32.u64 %0, t; }" : "=r"(a) : "l"(p));
    return a;
}
__device__ __forceinline__ void cp16(uint32_t dst, const void* src) {
    asm volatile("cp.async.cg.shared.global [%0], [%1], 16;" :: "r"(dst), "l"(src));
}
#define CP_COMMIT() asm volatile("cp.async.commit_group;" ::: "memory")
#define CP_WAIT(n)  asm volatile("cp.async.wait_group %0;" :: "n"(n) : "memory")

__device__ __forceinline__ uint32_t f2tf(float f) {
    uint32_t u; asm("cvt.rna.tf32.f32 %0, %1;" : "=r"(u) : "f"(f)); return u;
}
__device__ __forceinline__ float roundtf(float f) { return __uint_as_float(f2tf(f)); }

__device__ __forceinline__ void mma_tf32(float* c, const uint32_t* a, const uint32_t* b) {
    asm volatile(
        "mma.sync.aligned.m16n8k8.row.col.f32.tf32.tf32.f32 "
        "{%0,%1,%2,%3}, {%4,%5,%6,%7}, {%8,%9}, {%0,%1,%2,%3};"
        : "+f"(c[0]), "+f"(c[1]), "+f"(c[2]), "+f"(c[3])
        : "r"(a[0]), "r"(a[1]), "r"(a[2]), "r"(a[3]), "r"(b[0]), "r"(b[1]));
}

// ---------------- epilogues ----------------
template <int EPI>
__device__ __forceinline__ float apply_epi(float acc, const float* __restrict__ bias, int col) {
    if (EPI == 1) return acc + bias[col];
    if (EPI == 2) {
        float v = acc + 2.0f * bias[col];
        return fmaxf(v, 0.0f) + log1pf(expf(-fabsf(v)));
    }
    return acc;
}

// ================= tf32 mma.sync GEMM =================
// C[M,N] = A[M,K] @ Bt[N,K]^T. CTA 128x128, BK=32, 256 thr, warp tile 64x32.
// 3-stage cp.async pipeline. B (weights) is pre-rounded to tf32; A is either
// pre-rounded (CVTA=false -> raw bit loads) or converted in-loop (CVTA=true).
#define GSM_STAGE 4096                       // floats per tile stage (128*32)
#define GSM_TOTAL (6 * GSM_STAGE * 4)        // bytes: 3 stages A + 3 stages B

template <int EPI, bool CVTA>
__global__ __launch_bounds__(256)
void gemm_mma(const float* __restrict__ A, const float* __restrict__ Bt,
              float* __restrict__ C, const float* __restrict__ bias,
              int M, int N, int K, int lda, int ldb, int ldc)
{
    extern __shared__ float sm[];
    float* sA = sm;                  // 3 x 4096 floats
    float* sB = sm + 3 * GSM_STAGE;  // 3 x 4096 floats

    const int tid = threadIdx.x;
    const int wid = tid >> 5, lane = tid & 31;
    const int g = lane >> 2, tg = lane & 3;
    const int wm = wid & 1, wn = wid >> 1;      // 2 x 4 warp grid
    const int row0 = blockIdx.y * 128;
    const int col0 = blockIdx.x * 128;

    float acc[4][4][4];
#pragma unroll
    for (int i = 0; i < 4; ++i)
#pragma unroll
        for (int j = 0; j < 4; ++j)
#pragma unroll
            for (int c = 0; c < 4; ++c) acc[i][j][c] = 0.0f;

    const uint32_t sAu = smem_u32(sA);
    const uint32_t sBu = smem_u32(sB);

    const int cm = tid >> 3, cc = tid & 7;
    auto load_stage = [&](int s, int kt) {
        uint32_t ab = sAu + s * (GSM_STAGE * 4);
        uint32_t bb = sBu + s * (GSM_STAGE * 4);
        const int k0 = kt * 32;
#pragma unroll
        for (int i = 0; i < 4; ++i) {
            int m = cm + i * 32;
            cp16(ab + m * 128 + ((cc ^ (m & 7)) * 16),
                 A + (size_t)(row0 + m) * lda + k0 + cc * 4);
        }
#pragma unroll
        for (int i = 0; i < 4; ++i) {
            int n = cm + i * 32;
            if (col0 + n < N)
                cp16(bb + n * 128 + ((cc ^ (n & 7)) * 16),
                     Bt + (size_t)(col0 + n) * ldb + k0 + cc * 4);
        }
    };

    const int KT = K >> 5;   // >= 2 for all our GEMMs
    load_stage(0, 0); CP_COMMIT();
    load_stage(1, 1); CP_COMMIT();

    int am[4][2];
#pragma unroll
    for (int mt = 0; mt < 4; ++mt) {
        am[mt][0] = (wm * 64 + mt * 16 + g) * 32;
        am[mt][1] = (wm * 64 + mt * 16 + g + 8) * 32;
    }
    int bn[4];
#pragma unroll
    for (int nt = 0; nt < 4; ++nt) bn[nt] = (wn * 32 + nt * 8 + g) * 32;

    int s = 0, pf = 2;   // current stage, prefetch stage = (kt+2)%3
    for (int kt = 0; kt < KT; ++kt) {
        if (kt + 2 < KT) { load_stage(pf, kt + 2); CP_COMMIT(); CP_WAIT(2); }
        else if (kt + 1 < KT) { CP_WAIT(1); }
        else { CP_WAIT(0); }
        __syncthreads();

        const float* a_s = sA + s * GSM_STAGE;
        const float* b_s = sB + s * GSM_STAGE;
#pragma unroll
        for (int ks = 0; ks < 4; ++ks) {
            const int sw0 = ((2 * ks) ^ g) * 4 + tg;
            const int sw1 = ((2 * ks + 1) ^ g) * 4 + tg;
            uint32_t afr[4][4], bfr[4][2];
#pragma unroll
            for (int mt = 0; mt < 4; ++mt) {
                if (CVTA) {
                    afr[mt][0] = f2tf(a_s[am[mt][0] + sw0]);
                    afr[mt][1] = f2tf(a_s[am[mt][1] + sw0]);
                    afr[mt][2] = f2tf(a_s[am[mt][0] + sw1]);
                    afr[mt][3] = f2tf(a_s[am[mt][1] + sw1]);
                } else {
                    afr[mt][0] = __float_as_uint(a_s[am[mt][0] + sw0]);
                    afr[mt][1] = __float_as_uint(a_s[am[mt][1] + sw0]);
                    afr[mt][2] = __float_as_uint(a_s[am[mt][0] + sw1]);
                    afr[mt][3] = __float_as_uint(a_s[am[mt][1] + sw1]);
                }
            }
#pragma unroll
            for (int nt = 0; nt < 4; ++nt) {
                bfr[nt][0] = __float_as_uint(b_s[bn[nt] + sw0]);
                bfr[nt][1] = __float_as_uint(b_s[bn[nt] + sw1]);
            }
#pragma unroll
            for (int mt = 0; mt < 4; ++mt)
#pragma unroll
                for (int nt = 0; nt < 4; ++nt)
                    mma_tf32(acc[mt][nt], afr[mt], bfr[nt]);
        }
        __syncthreads();
        s = (s == 2) ? 0 : s + 1;
        pf = (pf == 2) ? 0 : pf + 1;
    }

    // epilogue
#pragma unroll
    for (int mt = 0; mt < 4; ++mt) {
#pragma unroll
        for (int h = 0; h < 2; ++h) {
            const int row = row0 + wm * 64 + mt * 16 + g + h * 8;
            float* cr = C + (size_t)row * ldc;
#pragma unroll
            for (int nt = 0; nt < 4; ++nt) {
                const int col = col0 + wn * 32 + nt * 8 + tg * 2;
                if (col < N) {
                    float2 v;
                    v.x = apply_epi<EPI>(acc[mt][nt][h * 2 + 0], bias, col);
                    v.y = apply_epi<EPI>(acc[mt][nt][h * 2 + 1], bias, col + 1);
                    *reinterpret_cast<float2*>(cr + col) = v;
                }
            }
        }
    }
}

// ================= transpose + tf32 round: out[c][r] = round(in[r][c]) =================
__global__ __launch_bounds__(256)
void transpose_kernel(const float* __restrict__ in, float* __restrict__ out, int R, int Cc)
{
    __shared__ float t[32][33];
    const int r0 = blockIdx.y * 32, c0 = blockIdx.x * 32;
    const int tx = threadIdx.x, ty = threadIdx.y;
    for (int j = ty; j < 32; j += 8)
        if (r0 + j < R && c0 + tx < Cc)
            t[j][tx] = roundtf(in[(size_t)(r0 + j) * Cc + c0 + tx]);
    __syncthreads();
    for (int j = ty; j < 32; j += 8)
        if (c0 + j < Cc && r0 + tx < R)
            out[(size_t)(c0 + j) * R + r0 + tx] = t[tx][j];
}

// ================= tf32 rounding pass (for x) =================
__global__ __launch_bounds__(256)
void round_kernel(const float* __restrict__ in, float* __restrict__ out, int n4)
{
    for (int i = blockIdx.x * blockDim.x + threadIdx.x; i < n4; i += gridDim.x * blockDim.x) {
        float4 v = reinterpret_cast<const float4*>(in)[i];
        v.x = roundtf(v.x); v.y = roundtf(v.y); v.z = roundtf(v.z); v.w = roundtf(v.w);
        reinterpret_cast<float4*>(out)[i] = v;
    }
}

// ================= depthwise conv (k=4, SAME pad_lo=1) + SiLU =================
__global__ __launch_bounds__(256)
void conv_silu_kernel(int col_off, const float* __restrict__ w,
                      const float* __restrict__ bias,
                      float* __restrict__ out, int out_ld, int out_coloff, int do_round)
{
    __shared__ float tile[67][128];
    const int c_t = blockIdx.x, t_t = blockIdx.y, b = blockIdx.z;
    const int tx = threadIdx.x, ty = threadIdx.y;
    const int c = c_t * 128 + tx;
    const int t0 = t_t * 64;

    const float* src = g_xz + (size_t)b * LSEQ * DINNER + col_off + c;
    for (int r = ty; r < 67; r += 2) {
        int t = t0 + r - 1;
        tile[r][tx] = (t >= 0 && t < LSEQ) ? src[(size_t)t * DINNER] : 0.0f;
    }
    __syncthreads();

    const float w0 = w[c], w1 = w[DHALF + c], w2 = w[2 * DHALF + c], w3 = w[3 * DHALF + c];
    const float bb = bias[c];
    float* dst = out + (size_t)b * LSEQ * out_ld + out_coloff + c;
    for (int tt = ty; tt < 64; tt += 2) {
        float v = bb;
        v = fmaf(w0, tile[tt + 0][tx], v);
        v = fmaf(w1, tile[tt + 1][tx], v);
        v = fmaf(w2, tile[tt + 2][tx], v);
        v = fmaf(w3, tile[tt + 3][tx], v);
        float sv = v / (1.0f + expf(-v));
        dst[(size_t)(t0 + tt) * out_ld] = do_round ? roundtf(sv) : sv;
    }
}

// ================= selective scan =================
__global__ __launch_bounds__(256)
void scan_kernel(const float* __restrict__ Dvec)
{
    const int grp = blockIdx.x * 16 + (threadIdx.x >> 4);
    const int n = threadIdx.x & 15;
    const int b = grp >> 10;
    const int d = grp & 1023;

    const float An = -(float)(n + 1);
    const float Dd = Dvec[d];

    const float* pD = g_delta + (size_t)b * LSEQ * DHALF + d;
    const float* pU = g_xs    + (size_t)b * LSEQ * DHALF + d;
    const float* pB = g_xdbl  + (size_t)b * LSEQ * XDBL_C + DTRANK + n;
    const float* pC = pB + DSTATE;
    float*       pY = g_cat   + (size_t)b * LSEQ * DINNER + d;

    float h = 0.0f;
    for (int t0 = 0; t0 < LSEQ; t0 += 8) {
        float dv[8], uv[8], Bv[8], Cv[8];
#pragma unroll
        for (int i = 0; i < 8; ++i) {
            dv[i] = pD[(size_t)(t0 + i) * DHALF];
            uv[i] = pU[(size_t)(t0 + i) * DHALF];
            Bv[i] = pB[(size_t)(t0 + i) * XDBL_C];
            Cv[i] = pC[(size_t)(t0 + i) * XDBL_C];
        }
#pragma unroll
        for (int i = 0; i < 8; ++i) {
            float dA = __expf(An * dv[i]);
            h = fmaf(dA, h, dv[i] * uv[i] * Bv[i]);
            float v = h * Cv[i];
            v += __shfl_xor_sync(0xffffffffu, v, 1);
            v += __shfl_xor_sync(0xffffffffu, v, 2);
            v += __shfl_xor_sync(0xffffffffu, v, 4);
            v += __shfl_xor_sync(0xffffffffu, v, 8);
            if (n == 0) pY[(size_t)(t0 + i) * DINNER] = roundtf(fmaf(uv[i], Dd, v));
        }
    }
}

// ================= launch =================
extern "C" void kernel_launch(void* const* d_in, const int* in_sizes, int n_in,
                              void* d_out, int out_size)
{
    const float* x      = (const float*)d_in[0];
    const float* W_in   = (const float*)d_in[1];
    const float* cxw    = (const float*)d_in[2];
    const float* cxb    = (const float*)d_in[3];
    const float* czw    = (const float*)d_in[4];
    const float* czb    = (const float*)d_in[5];
    const float* W_xdbl = (const float*)d_in[6];
    const float* W_dt   = (const float*)d_in[7];
    const float* inv_dt = (const float*)d_in[8];
    const float* Dv     = (const float*)d_in[9];
    const float* W_out  = (const float*)d_in[10];
    const float* b_out  = (const float*)d_in[11];
    float* out = (float*)d_out;

    float *xr, *xz, *xs, *xdbl, *delta, *cat, *WinT, *WxT, *WdtT, *WoutT;
    cudaGetSymbolAddress((void**)&xr,    g_xr);
    cudaGetSymbolAddress((void**)&xz,    g_xz);
    cudaGetSymbolAddress((void**)&xs,    g_xs);
    cudaGetSymbolAddress((void**)&xdbl,  g_xdbl);
    cudaGetSymbolAddress((void**)&delta, g_delta);
    cudaGetSymbolAddress((void**)&cat,   g_cat);
    cudaGetSymbolAddress((void**)&WinT,  g_WinT);
    cudaGetSymbolAddress((void**)&WxT,   g_WxT);
    cudaGetSymbolAddress((void**)&WdtT,  g_WdtT);
    cudaGetSymbolAddress((void**)&WoutT, g_WoutT);

    cudaFuncSetAttribute((const void*)gemm_mma<0, false>, cudaFuncAttributeMaxDynamicSharedMemorySize, GSM_TOTAL);
    cudaFuncSetAttribute((const void*)gemm_mma<0, true>,  cudaFuncAttributeMaxDynamicSharedMemorySize, GSM_TOTAL);
    cudaFuncSetAttribute((const void*)gemm_mma<1, false>, cudaFuncAttributeMaxDynamicSharedMemorySize, GSM_TOTAL);
    cudaFuncSetAttribute((const void*)gemm_mma<2, true>,  cudaFuncAttributeMaxDynamicSharedMemorySize, GSM_TOTAL);

    // 0) round x to tf32; transpose+round weights -> [N][K] K-major
    round_kernel<<<2048, 256>>>(x, xr, MROWS * DMODEL / 4);
    transpose_kernel<<<dim3(DINNER / 32, DMODEL / 32), dim3(32, 8)>>>(W_in, WinT, DMODEL, DINNER);
    transpose_kernel<<<dim3(XDBL_C / 32, DHALF / 32), dim3(32, 8)>>>(W_xdbl, WxT, DHALF, XDBL_C);
    transpose_kernel<<<dim3(DHALF / 32, DTRANK / 32), dim3(32, 8)>>>(W_dt, WdtT, DTRANK, DHALF);
    transpose_kernel<<<dim3(DMODEL / 32, DINNER / 32), dim3(32, 8)>>>(W_out, WoutT, DINNER, DMODEL);

    // 1) xz = x @ W_in        (8192 x 2048, K=1024)  [A pre-rounded]
    gemm_mma<0, false><<<dim3(DINNER / 128, MROWS / 128), 256, GSM_TOTAL>>>(
        xr, WinT, xz, nullptr, MROWS, DINNER, DMODEL, DMODEL, DMODEL, DINNER);

    // 2) depthwise conv + SiLU (xs kept full precision for the scan; z pre-rounded)
    conv_silu_kernel<<<dim3(8, 32, 4), dim3(128, 2)>>>(0,     cxw, cxb, xs,  DHALF,  0,     0);
    conv_silu_kernel<<<dim3(8, 32, 4), dim3(128, 2)>>>(DHALF, czw, czb, cat, DINNER, DHALF, 1);

    // 3) x_dbl = xs @ W_xdbl  (8192 x 96, K=1024)  [A converted in-loop]
    gemm_mma<0, true><<<dim3(1, MROWS / 128), 256, GSM_TOTAL>>>(
        xs, WxT, xdbl, nullptr, MROWS, XDBL_C, DHALF, DHALF, DHALF, XDBL_C);

    // 4) delta = softplus(dt_low @ W_dt + 2*inv_dt)   (8192 x 1024, K=64)  [A in-loop]
    gemm_mma<2, true><<<dim3(DHALF / 128, MROWS / 128), 256, GSM_TOTAL>>>(
        xdbl, WdtT, delta, inv_dt, MROWS, DHALF, DTRANK, XDBL_C, DTRANK, DHALF);

    // 5) selective scan -> y (tf32-rounded) into g_cat[:, 0:1024]
    scan_kernel<<<256, 256>>>(Dv);

    // 6) out = [y | z] @ W_out + b_out   (8192 x 1024, K=2048)  [A pre-rounded]
    gemm_mma<1, false><<<dim3(DMODEL / 128, MROWS / 128), 256, GSM_TOTAL>>>(
        cat, WoutT, out, b_out, MROWS, DMODEL, DINNER, DINNER, DINNER, DMODEL);
}

// round 9
// speedup vs baseline: 2.9869x; 1.0999x over previous
#include <cuda_runtime.h>
#include <cuda_fp16.h>
#include <cstdint>
#include <math.h>

#define B_SZ   4
#define LSEQ   2048
#define DMODEL 1024
#define DINNER 2048
#define DHALF  1024
#define DSTATE 16
#define DTRANK 64
#define XDBL_C 96
#define MROWS  (B_SZ * LSEQ)   // 8192

// ---------------- scratch (static device arrays; no allocation) ----------------
__device__ __half g_xh  [(size_t)MROWS * DMODEL];   // half(x)
__device__ float  g_xz  [(size_t)MROWS * DINNER];   // x @ W_in (float)
__device__ float  g_xs  [(size_t)MROWS * DHALF];    // silu(conv(xs)) float (scan u)
__device__ __half g_xsh [(size_t)MROWS * DHALF];    // same, half (GEMM3 A)
__device__ float  g_xdbl[(size_t)MROWS * XDBL_C];   // xs @ W_xdbl (float, scan B/C)
__device__ __half g_dth [(size_t)MROWS * DTRANK];   // half(xdbl[:, :64]) (dt GEMM A)
__device__ float  g_delta[(size_t)MROWS * DHALF];   // softplus(...)
__device__ __half g_cath[(size_t)MROWS * DINNER];   // [y | z] half (GEMM4 A)
__device__ __half g_WinTh [(size_t)DINNER * DMODEL];
__device__ __half g_WxTh  [(size_t)XDBL_C * DHALF];
__device__ __half g_WdtTh [(size_t)DHALF * DTRANK];
__device__ __half g_WoutTh[(size_t)DMODEL * DINNER];

// ================= helpers =================
__device__ __forceinline__ uint32_t smem_u32(const void* p) {
    uint32_t a;
    asm("{ .reg .u64 t; cvta.to.shared.u64 t, %1; cvt.u32.u64 %0, t; }" : "=r"(a) : "l"(p));
    return a;
}
__device__ __forceinline__ void cp16(uint32_t dst, const void* src) {
    asm volatile("cp.async.cg.shared.global [%0], [%1], 16;" :: "r"(dst), "l"(src));
}
#define CP_COMMIT() asm volatile("cp.async.commit_group;" ::: "memory")
#define CP_WAIT(n)  asm volatile("cp.async.wait_group %0;" :: "n"(n) : "memory")

__device__ __forceinline__ void ldsm4(uint32_t* r, uint32_t addr) {
    asm volatile("ldmatrix.sync.aligned.m8n8.x4.shared.b16 {%0,%1,%2,%3}, [%4];"
        : "=r"(r[0]), "=r"(r[1]), "=r"(r[2]), "=r"(r[3]) : "r"(addr));
}
__device__ __forceinline__ void mma_f16(float* c, const uint32_t* a, uint32_t b0, uint32_t b1) {
    asm volatile(
        "mma.sync.aligned.m16n8k16.row.col.f32.f16.f16.f32 "
        "{%0,%1,%2,%3}, {%4,%5,%6,%7}, {%8,%9}, {%0,%1,%2,%3};"
        : "+f"(c[0]), "+f"(c[1]), "+f"(c[2]), "+f"(c[3])
        : "r"(a[0]), "r"(a[1]), "r"(a[2]), "r"(a[3]), "r"(b0), "r"(b1));
}

// ---------------- epilogues ----------------
template <int EPI>
__device__ __forceinline__ float apply_epi(float acc, const float* __restrict__ bias, int col) {
    if (EPI == 1) return acc + bias[col];
    if (EPI == 2) {
        float v = acc + 2.0f * bias[col];
        return fmaxf(v, 0.0f) + log1pf(expf(-fabsf(v)));
    }
    return acc;
}

// ================= fp16 mma.sync GEMM =================
// C[M,N] = A[M,K] @ Bt[N,K]^T, half in, fp32 accum/out. CTA 128x128, BK=32,
// 256 thr, warp tile 64x32. Smem rows: 64B data + 16B pad = 80B (conflict-free
// ldmatrix: row starts cover all 8 multiples-of-4 banks). 3-stage cp.async.
#define HSTAGE 10240                         // bytes per tile stage (128 rows x 80B)
#define HSM_TOTAL (6 * HSTAGE)               // 3 stages A + 3 stages B = 60 KB

template <int EPI>
__global__ __launch_bounds__(256)
void gemm_mma(const __half* __restrict__ A, const __half* __restrict__ Bt,
              float* __restrict__ C, const float* __restrict__ bias,
              int M, int N, int K, int lda, int ldb, int ldc)
{
    extern __shared__ char smc[];
    const uint32_t sAu = smem_u32(smc);
    const uint32_t sBu = sAu + 3 * HSTAGE;

    const int tid = threadIdx.x;
    const int wid = tid >> 5, lane = tid & 31;
    const int g = lane >> 2, tg = lane & 3;
    const int wm = wid & 1, wn = wid >> 1;      // 2 x 4 warp grid
    const int row0 = blockIdx.y * 128;
    const int col0 = blockIdx.x * 128;

    float acc[4][4][4];
#pragma unroll
    for (int i = 0; i < 4; ++i)
#pragma unroll
        for (int j = 0; j < 4; ++j)
#pragma unroll
            for (int c = 0; c < 4; ++c) acc[i][j][c] = 0.0f;

    // gmem -> smem copy: 128 rows x 4 chunks(16B) per operand per stage
    const int rm = tid >> 2, cc = tid & 3;
    auto load_stage = [&](int s, int kt) {
        const uint32_t ab = sAu + s * HSTAGE;
        const uint32_t bb = sBu + s * HSTAGE;
        const int k0 = kt * 32;
#pragma unroll
        for (int i = 0; i < 2; ++i) {
            int m = rm + i * 64;
            cp16(ab + m * 80 + cc * 16, A + (size_t)(row0 + m) * lda + k0 + cc * 8);
        }
#pragma unroll
        for (int i = 0; i < 2; ++i) {
            int n = rm + i * 64;
            if (col0 + n < N)
                cp16(bb + n * 80 + cc * 16, Bt + (size_t)(col0 + n) * ldb + k0 + cc * 8);
        }
    };

    const int KT = K >> 5;   // >= 2 for all our GEMMs
    load_stage(0, 0); CP_COMMIT();
    load_stage(1, 1); CP_COMMIT();

    // ldmatrix per-lane address offsets
    const int lrow = (lane & 7) + (lane & 8);        // matrix row supplied by this lane
    const int lhi  = (lane >> 4) & 1;                // +16B for k8-15 matrices
    const uint32_t aoffs = (uint32_t)((wm * 64 + lrow) * 80 + lhi * 16);
    const uint32_t boffs = (uint32_t)((wn * 32 + lrow) * 80 + lhi * 16);

    int s = 0, pf = 2;
    for (int kt = 0; kt < KT; ++kt) {
        if (kt + 2 < KT)      { load_stage(pf, kt + 2); CP_COMMIT(); CP_WAIT(2); }
        else if (kt + 1 < KT) { CP_WAIT(1); }
        else                  { CP_WAIT(0); }
        __syncthreads();

        const uint32_t abase = sAu + s * HSTAGE + aoffs;
        const uint32_t bbase = sBu + s * HSTAGE + boffs;
#pragma unroll
        for (int ks = 0; ks < 2; ++ks) {
            uint32_t af[4][4], bf[2][4];
#pragma unroll
            for (int mt = 0; mt < 4; ++mt)
                ldsm4(af[mt], abase + mt * (16 * 80) + ks * 32);
#pragma unroll
            for (int pr = 0; pr < 2; ++pr)
                ldsm4(bf[pr], bbase + pr * (16 * 80) + ks * 32);
#pragma unroll
            for (int mt = 0; mt < 4; ++mt)
#pragma unroll
                for (int nt = 0; nt < 4; ++nt)
                    mma_f16(acc[mt][nt], af[mt], bf[nt >> 1][nt & 1], bf[nt >> 1][2 + (nt & 1)]);
        }
        __syncthreads();
        s = (s == 2) ? 0 : s + 1;
        pf = (pf == 2) ? 0 : pf + 1;
    }

    // epilogue (C layout of m16n8k16 == m16n8k8: c0,c1=row g; c2,c3=row g+8)
#pragma unroll
    for (int mt = 0; mt < 4; ++mt) {
#pragma unroll
        for (int h = 0; h < 2; ++h) {
            const int row = row0 + wm * 64 + mt * 16 + g + h * 8;
            float* cr = C + (size_t)row * ldc;
#pragma unroll
            for (int nt = 0; nt < 4; ++nt) {
                const int col = col0 + wn * 32 + nt * 8 + tg * 2;
                if (col < N) {
                    float2 v;
                    v.x = apply_epi<EPI>(acc[mt][nt][h * 2 + 0], bias, col);
                    v.y = apply_epi<EPI>(acc[mt][nt][h * 2 + 1], bias, col + 1);
                    *reinterpret_cast<float2*>(cr + col) = v;
                }
            }
        }
    }
}

// ================= transpose + f16 round: out[c][r] = half(in[r][c]) =================
__global__ __launch_bounds__(256)
void transpose_h_kernel(const float* __restrict__ in, __half* __restrict__ out, int R, int Cc)
{
    __shared__ float t[32][33];
    const int r0 = blockIdx.y * 32, c0 = blockIdx.x * 32;
    const int tx = threadIdx.x, ty = threadIdx.y;
    for (int j = ty; j < 32; j += 8)
        if (r0 + j < R && c0 + tx < Cc)
            t[j][tx] = in[(size_t)(r0 + j) * Cc + c0 + tx];
    __syncthreads();
    for (int j = ty; j < 32; j += 8)
        if (c0 + j < Cc && r0 + tx < R)
            out[(size_t)(c0 + j) * R + r0 + tx] = __float2half(t[tx][j]);
}

// ================= float -> half pass (for x) =================
__global__ __launch_bounds__(256)
void f2h_kernel(const float* __restrict__ in, __half* __restrict__ out, int n4)
{
    for (int i = blockIdx.x * blockDim.x + threadIdx.x; i < n4; i += gridDim.x * blockDim.x) {
        float4 v = reinterpret_cast<const float4*>(in)[i];
        __half2 h0 = __floats2half2_rn(v.x, v.y);
        __half2 h1 = __floats2half2_rn(v.z, v.w);
        uint2 u;
        u.x = *reinterpret_cast<uint32_t*>(&h0);
        u.y = *reinterpret_cast<uint32_t*>(&h1);
        reinterpret_cast<uint2*>(out)[i] = u;
    }
}

// ================= xdbl[:, :64] -> half (dt GEMM A operand) =================
__global__ __launch_bounds__(256)
void dt2h_kernel(const float* __restrict__ in, __half* __restrict__ out)
{
    int idx = blockIdx.x * blockDim.x + threadIdx.x;   // over 8192*64
    int r = idx >> 6, c = idx & 63;
    out[idx] = __float2half(in[(size_t)r * XDBL_C + c]);
}

// ================= depthwise conv (k=4, SAME pad_lo=1) + SiLU =================
__global__ __launch_bounds__(256)
void conv_silu_kernel(int col_off, const float* __restrict__ w,
                      const float* __restrict__ bias,
                      float* __restrict__ outF, __half* __restrict__ outH,
                      int ldF, int ldH, int coloffH)
{
    __shared__ float tile[67][128];
    const int c_t = blockIdx.x, t_t = blockIdx.y, b = blockIdx.z;
    const int tx = threadIdx.x, ty = threadIdx.y;
    const int c = c_t * 128 + tx;
    const int t0 = t_t * 64;

    const float* src = g_xz + (size_t)b * LSEQ * DINNER + col_off + c;
    for (int r = ty; r < 67; r += 2) {
        int t = t0 + r - 1;
        tile[r][tx] = (t >= 0 && t < LSEQ) ? src[(size_t)t * DINNER] : 0.0f;
    }
    __syncthreads();

    const float w0 = w[c], w1 = w[DHALF + c], w2 = w[2 * DHALF + c], w3 = w[3 * DHALF + c];
    const float bb = bias[c];
    float*  dF = outF ? outF + (size_t)b * LSEQ * ldF + c : nullptr;
    __half* dH = outH ? outH + (size_t)b * LSEQ * ldH + coloffH + c : nullptr;
    for (int tt = ty; tt < 64; tt += 2) {
        float v = bb;
        v = fmaf(w0, tile[tt + 0][tx], v);
        v = fmaf(w1, tile[tt + 1][tx], v);
        v = fmaf(w2, tile[tt + 2][tx], v);
        v = fmaf(w3, tile[tt + 3][tx], v);
        float sv = v / (1.0f + expf(-v));
        if (dF) dF[(size_t)(t0 + tt) * ldF] = sv;
        if (dH) dH[(size_t)(t0 + tt) * ldH] = __float2half(sv);
    }
}

// ================= selective scan (y written as half into g_cath) =================
__global__ __launch_bounds__(256)
void scan_kernel(const float* __restrict__ Dvec)
{
    const int grp = blockIdx.x * 16 + (threadIdx.x >> 4);
    const int n = threadIdx.x & 15;
    const int b = grp >> 10;
    const int d = grp & 1023;

    const float An = -(float)(n + 1);
    const float Dd = Dvec[d];

    const float* pD = g_delta + (size_t)b * LSEQ * DHALF + d;
    const float* pU = g_xs    + (size_t)b * LSEQ * DHALF + d;
    const float* pB = g_xdbl  + (size_t)b * LSEQ * XDBL_C + DTRANK + n;
    const float* pC = pB + DSTATE;
    __half*      pY = g_cath  + (size_t)b * LSEQ * DINNER + d;

    float h = 0.0f;
    for (int t0 = 0; t0 < LSEQ; t0 += 8) {
        float dv[8], uv[8], Bv[8], Cv[8];
#pragma unroll
        for (int i = 0; i < 8; ++i) {
            dv[i] = pD[(size_t)(t0 + i) * DHALF];
            uv[i] = pU[(size_t)(t0 + i) * DHALF];
            Bv[i] = pB[(size_t)(t0 + i) * XDBL_C];
            Cv[i] = pC[(size_t)(t0 + i) * XDBL_C];
        }
#pragma unroll
        for (int i = 0; i < 8; ++i) {
            float dA = __expf(An * dv[i]);
            h = fmaf(dA, h, dv[i] * uv[i] * Bv[i]);
            float v = h * Cv[i];
            v += __shfl_xor_sync(0xffffffffu, v, 1);
            v += __shfl_xor_sync(0xffffffffu, v, 2);
            v += __shfl_xor_sync(0xffffffffu, v, 4);
            v += __shfl_xor_sync(0xffffffffu, v, 8);
            if (n == 0) pY[(size_t)(t0 + i) * DINNER] = __float2half(fmaf(uv[i], Dd, v));
        }
    }
}

// ================= launch =================
extern "C" void kernel_launch(void* const* d_in, const int* in_sizes, int n_in,
                              void* d_out, int out_size)
{
    const float* x      = (const float*)d_in[0];
    const float* W_in   = (const float*)d_in[1];
    const float* cxw    = (const float*)d_in[2];
    const float* cxb    = (const float*)d_in[3];
    const float* czw    = (const float*)d_in[4];
    const float* czb    = (const float*)d_in[5];
    const float* W_xdbl = (const float*)d_in[6];
    const float* W_dt   = (const float*)d_in[7];
    const float* inv_dt = (const float*)d_in[8];
    const float* Dv     = (const float*)d_in[9];
    const float* W_out  = (const float*)d_in[10];
    const float* b_out  = (const float*)d_in[11];
    float* out = (float*)d_out;

    __half *xh, *xsh, *dth, *cath, *WinTh, *WxTh, *WdtTh, *WoutTh;
    float *xz, *xs, *xdbl, *delta;
    cudaGetSymbolAddress((void**)&xh,     g_xh);
    cudaGetSymbolAddress((void**)&xz,     g_xz);
    cudaGetSymbolAddress((void**)&xs,     g_xs);
    cudaGetSymbolAddress((void**)&xsh,    g_xsh);
    cudaGetSymbolAddress((void**)&xdbl,   g_xdbl);
    cudaGetSymbolAddress((void**)&dth,    g_dth);
    cudaGetSymbolAddress((void**)&delta,  g_delta);
    cudaGetSymbolAddress((void**)&cath,   g_cath);
    cudaGetSymbolAddress((void**)&WinTh,  g_WinTh);
    cudaGetSymbolAddress((void**)&WxTh,   g_WxTh);
    cudaGetSymbolAddress((void**)&WdtTh,  g_WdtTh);
    cudaGetSymbolAddress((void**)&WoutTh, g_WoutTh);

    cudaFuncSetAttribute((const void*)gemm_mma<0>, cudaFuncAttributeMaxDynamicSharedMemorySize, HSM_TOTAL);
    cudaFuncSetAttribute((const void*)gemm_mma<1>, cudaFuncAttributeMaxDynamicSharedMemorySize, HSM_TOTAL);
    cudaFuncSetAttribute((const void*)gemm_mma<2>, cudaFuncAttributeMaxDynamicSharedMemorySize, HSM_TOTAL);

    // 0) half(x); transpose+half weights -> [N][K] K-major
    f2h_kernel<<<2048, 256>>>(x, xh, MROWS * DMODEL / 4);
    transpose_h_kernel<<<dim3(DINNER / 32, DMODEL / 32), dim3(32, 8)>>>(W_in, WinTh, DMODEL, DINNER);
    transpose_h_kernel<<<dim3(XDBL_C / 32, DHALF / 32), dim3(32, 8)>>>(W_xdbl, WxTh, DHALF, XDBL_C);
    transpose_h_kernel<<<dim3(DHALF / 32, DTRANK / 32), dim3(32, 8)>>>(W_dt, WdtTh, DTRANK, DHALF);
    transpose_h_kernel<<<dim3(DMODEL / 32, DINNER / 32), dim3(32, 8)>>>(W_out, WoutTh, DINNER, DMODEL);

    // 1) xz = x @ W_in        (8192 x 2048, K=1024)
    gemm_mma<0><<<dim3(DINNER / 128, MROWS / 128), 256, HSM_TOTAL>>>(
        xh, WinTh, xz, nullptr, MROWS, DINNER, DMODEL, DMODEL, DMODEL, DINNER);

    // 2) depthwise conv + SiLU (xs -> float for scan + half for GEMM3; z -> half into cat)
    conv_silu_kernel<<<dim3(8, 32, 4), dim3(128, 2)>>>(0,     cxw, cxb, xs,      xsh,  DHALF,  DHALF,  0);
    conv_silu_kernel<<<dim3(8, 32, 4), dim3(128, 2)>>>(DHALF, czw, czb, nullptr, cath, 0,      DINNER, DHALF);

    // 3) x_dbl = xs @ W_xdbl  (8192 x 96, K=1024)
    gemm_mma<0><<<dim3(1, MROWS / 128), 256, HSM_TOTAL>>>(
        xsh, WxTh, xdbl, nullptr, MROWS, XDBL_C, DHALF, DHALF, DHALF, XDBL_C);

    // 3b) half copy of dt_low columns
    dt2h_kernel<<<MROWS * DTRANK / 256, 256>>>(xdbl, dth);

    // 4) delta = softplus(dt_low @ W_dt + 2*inv_dt)   (8192 x 1024, K=64)
    gemm_mma<2><<<dim3(DHALF / 128, MROWS / 128), 256, HSM_TOTAL>>>(
        dth, WdtTh, delta, inv_dt, MROWS, DHALF, DTRANK, DTRANK, DTRANK, DHALF);

    // 5) selective scan -> y (half) into g_cath[:, 0:1024]
    scan_kernel<<<256, 256>>>(Dv);

    // 6) out = [y | z] @ W_out + b_out   (8192 x 1024, K=2048)
    gemm_mma<1><<<dim3(DMODEL / 128, MROWS / 128), 256, HSM_TOTAL>>>(
        cath, WoutTh, out, b_out, MROWS, DMODEL, DINNER, DINNER, DINNER, DMODEL);
}